// round 17
// baseline (speedup 1.0000x reference)
#include <cuda_runtime.h>
#include <cuda_bf16.h>
#include <cuda_fp16.h>
#include <cstdint>
#include <string.h>
#include <math.h>

// ---------------- problem constants ----------------
#define D_MODEL  2048
#define N_HEADS  16
#define HEAD_DIM 128
#define BATCH    2
#define SEQ      2048
#define M_TOT    (BATCH * SEQ)      // 4096 rows
#define N_QKV    (3 * D_MODEL)      // 6144 fused QKV width
#define N_BH     (BATCH * N_HEADS)  // 32 head-batches

// ---------------- scratch (alloc-free rule: __device__ globals) ----------------
__device__ __half g_xf   [M_TOT * D_MODEL];         // x in fp16
__device__ __half g_cf   [M_TOT * D_MODEL];         // flash ctx (fp16, token-major)
__device__ __half g_Wqkvf[3 * D_MODEL * D_MODEL];   // [Wq;Wk;Wv] fp16
__device__ __half g_Wof  [D_MODEL * D_MODEL];

// head-major flash operands [bh][seq][128], all fp16
__device__ __half g_fQ[N_BH * SEQ * HEAD_DIM];
__device__ __half g_fK[N_BH * SEQ * HEAD_DIM];
__device__ __half g_fV[N_BH * SEQ * HEAD_DIM];

// rope table: [row 0..4095][i 0..63] -> (cos, sin)
__device__ float2 g_tab[M_TOT * 64];

// ============================================================================
// PTX helpers (compute_103-safe)
// ============================================================================
__device__ __forceinline__ uint32_t smem_u32(const void* p) {
    uint32_t a;
    asm("{ .reg .u64 t; cvta.to.shared.u64 t, %1; cvt.u32.u64 %0, t; }" : "=r"(a) : "l"(p));
    return a;
}
__device__ __forceinline__ void ldmatrix_x4(uint32_t* r, uint32_t addr) {
    asm volatile("ldmatrix.sync.aligned.m8n8.x4.shared.b16 {%0,%1,%2,%3}, [%4];"
                 : "=r"(r[0]), "=r"(r[1]), "=r"(r[2]), "=r"(r[3]) : "r"(addr));
}
__device__ __forceinline__ void ldmatrix_x4_t(uint32_t* r, uint32_t addr) {
    asm volatile("ldmatrix.sync.aligned.m8n8.x4.trans.shared.b16 {%0,%1,%2,%3}, [%4];"
                 : "=r"(r[0]), "=r"(r[1]), "=r"(r[2]), "=r"(r[3]) : "r"(addr));
}
__device__ __forceinline__ void mma_f16(float* c, const uint32_t* a, const uint32_t* b) {
    asm volatile(
        "mma.sync.aligned.m16n8k16.row.col.f32.f16.f16.f32 "
        "{%0,%1,%2,%3}, {%4,%5,%6,%7}, {%8,%9}, {%0,%1,%2,%3};"
        : "+f"(c[0]), "+f"(c[1]), "+f"(c[2]), "+f"(c[3])
        : "r"(a[0]), "r"(a[1]), "r"(a[2]), "r"(a[3]), "r"(b[0]), "r"(b[1]));
}
__device__ __forceinline__ void cp16(uint32_t s, const void* g) {
    asm volatile("cp.async.cg.shared.global [%0], [%1], 16;" :: "r"(s), "l"(g));
}
__device__ __forceinline__ void cp_commit() {
    asm volatile("cp.async.commit_group;" ::: "memory");
}
__device__ __forceinline__ void cp_wait_1() {
    asm volatile("cp.async.wait_group 1;" ::: "memory");
}
__device__ __forceinline__ void cp_wait_0() {
    asm volatile("cp.async.wait_group 0;" ::: "memory");
}
__device__ __forceinline__ uint32_t pack_h2(float a, float b) {
    __half2 h = __floats2half2_rn(a, b);
    uint32_t u; memcpy(&u, &h, 4);
    return u;
}

// ============================================================================
// conversions + rope table
// ============================================================================
__global__ void cvt_h_kernel(const float* __restrict__ in,
                             __half* __restrict__ out, int n4)
{
    int i = blockIdx.x * blockDim.x + threadIdx.x;
    if (i >= n4) return;
    float4 v = ((const float4*)in)[i];
    __half2* op = (__half2*)out;
    op[2*i]   = __floats2half2_rn(v.x, v.y);
    op[2*i+1] = __floats2half2_rn(v.z, v.w);
}

__global__ void cvt_w4_kernel(const float* __restrict__ wq, const float* __restrict__ wk,
                              const float* __restrict__ wv, const float* __restrict__ wo,
                              __half* __restrict__ qkv, __half* __restrict__ o, int n4each)
{
    int i = blockIdx.x * blockDim.x + threadIdx.x;
    if (i >= n4each) return;
    const float* in;
    __half* out;
    switch (blockIdx.y) {
        case 0: in = wq; out = qkv; break;
        case 1: in = wk; out = qkv + 1 * (size_t)D_MODEL * D_MODEL; break;
        case 2: in = wv; out = qkv + 2 * (size_t)D_MODEL * D_MODEL; break;
        default: in = wo; out = o; break;
    }
    float4 vv = ((const float4*)in)[i];
    __half2* op = (__half2*)out;
    op[2*i]   = __floats2half2_rn(vv.x, vv.y);
    op[2*i+1] = __floats2half2_rn(vv.z, vv.w);
}

__global__ void rope_tab_kernel(const int* __restrict__ pos, float2* __restrict__ tab)
{
    int idx = blockIdx.x * blockDim.x + threadIdx.x;
    if (idx >= M_TOT * 64) return;
    int i   = idx & 63;
    int row = idx >> 6;
    int p   = pos[row];
    float inv_freq = powf(10000.0f, -(2.0f * (float)i) / 128.0f);
    float sn, cs;
    sincosf((float)p * inv_freq, &sn, &cs);
    tab[idx] = make_float2(cs, sn);
}

// ============================================================================
// GEMM v3: CTA 128(M) x 256(N), 256 thr, 8 warps, warp tile 64x64.
// BK=64 (4 k16-steps/stage), 3-stage cp.async (48KB/stage, 144KB smem),
// 1 CTA/SM. Per ks-step: 8 LDSM feed 32 MMAs (1:4).
// SMEM rows 128B, swizzle ch ^= row&7.
// ============================================================================
#define BK64      64
#define NIT64     (D_MODEL / BK64)        // 32

__device__ __forceinline__ uint32_t sw64(int row, int ch) {
    return (uint32_t)(row * 128 + ((ch ^ (row & 7)) << 4));
}

#define T_A64     0                        // A tile: 128 rows x 128B = 16KB
#define T_B64     16384                    // B tile: 256 rows x 128B = 32KB
#define STAGE64   49152                    // 48 KB per stage
#define SMEM_G64  (3 * STAGE64 + 128)      // 144 KB + pad

__device__ __forceinline__ void issue_stage64(
    uint32_t stage,
    const __half* __restrict__ A, const __half* __restrict__ B,
    int bm, int bn, int k0, int tid)
{
#pragma unroll
    for (int j = 0; j < 4; j++) {
        int idx = tid + 256 * j;            // 0..1023 -> A 128 rows x 8 ch
        int row = idx >> 3;
        int ch  = idx & 7;
        cp16(stage + T_A64 + sw64(row, ch),
             A + (size_t)(bm + row) * D_MODEL + k0 + ch * 8);
    }
#pragma unroll
    for (int j = 0; j < 8; j++) {
        int idx = tid + 256 * j;            // 0..2047 -> B 256 rows x 8 ch
        int row = idx >> 3;
        int ch  = idx & 7;
        cp16(stage + T_B64 + sw64(row, ch),
             B + (size_t)(bn + row) * D_MODEL + k0 + ch * 8);
    }
}

// mainloop producing acc[4][8][4] (warp tile 64x64)
#define GEMM256_MAINLOOP(A, B)                                                \
    float acc[4][8][4];                                                       \
    _Pragma("unroll")                                                         \
    for (int mi = 0; mi < 4; mi++)                                            \
        _Pragma("unroll")                                                     \
        for (int ni = 0; ni < 8; ni++)                                        \
            _Pragma("unroll")                                                 \
            for (int r = 0; r < 4; r++) acc[mi][ni][r] = 0.f;                 \
    issue_stage64(sbase + 0 * STAGE64, A, B, bm, bn, 0, tid);                 \
    cp_commit();                                                              \
    issue_stage64(sbase + 1 * STAGE64, A, B, bm, bn, BK64, tid);              \
    cp_commit();                                                              \
    int buf = 0, ibuf = 2;                                                    \
    for (int c = 0; c < NIT64; c++) {                                         \
        cp_wait_1();                                                          \
        __syncthreads();                                                      \
        if (c + 2 < NIT64)                                                    \
            issue_stage64(sbase + (uint32_t)ibuf * STAGE64, A, B,             \
                          bm, bn, (c + 2) * BK64, tid);                       \
        cp_commit();                                                          \
        const uint32_t tA = sbase + (uint32_t)buf * STAGE64 + T_A64;          \
        const uint32_t tB = sbase + (uint32_t)buf * STAGE64 + T_B64;          \
        _Pragma("unroll")                                                     \
        for (int ks = 0; ks < 4; ks++) {                                      \
            uint32_t aF[4][4], bF[8][2];                                      \
            _Pragma("unroll")                                                 \
            for (int mi = 0; mi < 4; mi++)                                    \
                ldmatrix_x4(aF[mi], tA + sw64(wm + mi * 16 + aRowL, 2*ks + aChL)); \
            _Pragma("unroll")                                                 \
            for (int p = 0; p < 4; p++) {                                     \
                uint32_t t4[4];                                               \
                ldmatrix_x4(t4, tB + sw64(wn + p * 16 + bRowL, 2*ks + bChL)); \
                bF[2*p][0] = t4[0]; bF[2*p][1] = t4[1];                       \
                bF[2*p+1][0] = t4[2]; bF[2*p+1][1] = t4[3];                   \
            }                                                                 \
            _Pragma("unroll")                                                 \
            for (int mi = 0; mi < 4; mi++)                                    \
                _Pragma("unroll")                                             \
                for (int ni = 0; ni < 8; ni++)                                \
                    mma_f16(acc[mi][ni], aF[mi], bF[ni]);                     \
        }                                                                     \
        buf  = (buf == 2)  ? 0 : buf + 1;                                     \
        ibuf = (ibuf == 2) ? 0 : ibuf + 1;                                    \
    }

// Fused QKV projection (fp16, N=6144). CTA covers 256 cols (region-pure since
// region boundaries are multiples of 2048). Q/K epilogue applies RoPE.
__global__ void __launch_bounds__(256, 1) mma_gemmQKV_kernel(
    const __half* __restrict__ A, const __half* __restrict__ B,
    const float2* __restrict__ tab,
    __half* __restrict__ Qo, __half* __restrict__ Ko, __half* __restrict__ Vo)
{
    extern __shared__ char sm_raw[];
    const uint32_t sbase = (smem_u32(sm_raw) + 127u) & ~127u;

    const int tid  = threadIdx.x;
    const int lane = tid & 31;
    const int w    = tid >> 5;
    const int wm   = (w & 1) * 64;
    const int wn   = (w >> 1) * 64;       // 0/64/128/192
    const int bm   = blockIdx.y * 128;
    const int bn   = blockIdx.x * 256;    // [0, 6144)

    const int g  = lane >> 3;
    const int li = lane & 7;
    const int aRowL = li + ((g & 1) << 3);
    const int aChL  = g >> 1;
    const int bRowL = li + ((g >> 1) << 3);
    const int bChL  = g & 1;

    GEMM256_MAINLOOP(A, B)

    const int gid = lane >> 2;
    const int tig = lane & 3;
    const int region = bn >> 11;           // 0=Q, 1=K, 2=V
    __half* Out = (region == 0) ? Qo : (region == 1) ? Ko : Vo;
    const bool doRope = (region < 2);

#pragma unroll
    for (int mi = 0; mi < 4; mi++) {
        const int r0 = bm + wm + mi * 16 + gid;
        const int r1 = r0 + 8;
        const int b0 = r0 >> 11, s0 = r0 & 2047;
        const int b1 = r1 >> 11, s1 = r1 & 2047;
#pragma unroll
        for (int ni = 0; ni < 8; ni++) {
            int col = bn + wn + ni * 8 + tig * 2;
            int cc  = col & 2047;
            int h   = cc >> 7;
            int d   = cc & 127;
            float e0 = acc[mi][ni][0], o0 = acc[mi][ni][1];
            float e1 = acc[mi][ni][2], o1 = acc[mi][ni][3];
            if (doRope) {
                int i = d >> 1;
                float2 cs0 = tab[r0 * 64 + i];
                float2 cs1 = tab[r1 * 64 + i];
                float t;
                t  = e0 * cs0.x - o0 * cs0.y;
                o0 = e0 * cs0.y + o0 * cs0.x; e0 = t;
                t  = e1 * cs1.x - o1 * cs1.y;
                o1 = e1 * cs1.y + o1 * cs1.x; e1 = t;
            }
            size_t d0 = ((size_t)((b0 * N_HEADS + h) * SEQ + s0)) * HEAD_DIM + d;
            size_t d1 = ((size_t)((b1 * N_HEADS + h) * SEQ + s1)) * HEAD_DIM + d;
            *(__half2*)(Out + d0) = __floats2half2_rn(e0, o0);
            *(__half2*)(Out + d1) = __floats2half2_rn(e1, o1);
        }
    }
}

// fp16 GEMM, fp32 token-major epilogue (output projection)
__global__ void __launch_bounds__(256, 1) mma_gemm1_kernel(
    const __half* __restrict__ A, const __half* __restrict__ B,
    float* __restrict__ C, int ldc)
{
    extern __shared__ char sm_raw[];
    const uint32_t sbase = (smem_u32(sm_raw) + 127u) & ~127u;

    const int tid  = threadIdx.x;
    const int lane = tid & 31;
    const int w    = tid >> 5;
    const int wm   = (w & 1) * 64;
    const int wn   = (w >> 1) * 64;
    const int bm   = blockIdx.y * 128;
    const int bn   = blockIdx.x * 256;

    const int g  = lane >> 3;
    const int li = lane & 7;
    const int aRowL = li + ((g & 1) << 3);
    const int aChL  = g >> 1;
    const int bRowL = li + ((g >> 1) << 3);
    const int bChL  = g & 1;

    GEMM256_MAINLOOP(A, B)

    const int gid = lane >> 2;
    const int tig = lane & 3;
#pragma unroll
    for (int mi = 0; mi < 4; mi++) {
#pragma unroll
        for (int ni = 0; ni < 8; ni++) {
            int row = bm + wm + mi * 16 + gid;
            int col = bn + wn + ni * 8 + tig * 2;
            float2 v0 = make_float2(acc[mi][ni][0], acc[mi][ni][1]);
            float2 v1 = make_float2(acc[mi][ni][2], acc[mi][ni][3]);
            *(float2*)(C + (size_t)row * ldc + col) = v0;
            *(float2*)(C + (size_t)(row + 8) * ldc + col) = v1;
        }
    }
}

// ============================================================================
// flash v4 (verified R15/R16): all-fp16 tensor-core causal attention.
// CTA: 64 queries x 1 head, 128 threads, 48KB smem -> 3 CTAs/SM.
// ============================================================================
#define FQ 0
#define FK 16384
#define FV 32768
#define SMEM_FLASH (49152 + 128)

__device__ __forceinline__ uint32_t fsw(int row, int ch) {
    return (uint32_t)(row * 256 + ((ch ^ (row & 7)) << 4));
}

__global__ void __launch_bounds__(128, 3) flash2_kernel(
    const __half* __restrict__ Q, const __half* __restrict__ K,
    const __half* __restrict__ V,
    __half* __restrict__ Ctx)
{
    extern __shared__ char sm_raw[];
    const uint32_t sb = (smem_u32(sm_raw) + 127u) & ~127u;

    const int tid  = threadIdx.x;
    const int lane = tid & 31;
    const int w    = tid >> 5;
    const int bh   = blockIdx.y;
    const int q0   = (gridDim.x - 1 - blockIdx.x) * 64;
    const size_t hbase = (size_t)bh * SEQ * HEAD_DIM;

    const int g2 = lane >> 3, li = lane & 7;
    const int aRow = w * 16 + ((g2 & 1) << 3) + li;
    const int aChS = g2 >> 1;
    const int bRowK = ((g2 >> 1) << 3) + li;
    const int bChK  = g2 & 1;
    const int vRowS = ((g2 & 1) << 3) + li;
    const int vChS  = g2 >> 1;
    const int gid = lane >> 2, tig = lane & 3;

#pragma unroll
    for (int j = 0; j < 8; j++) {
        int idx = tid + 128 * j; int row = idx >> 4; int ch = idx & 15;
        uint32_t so = fsw(row, ch);
        size_t gq = hbase + (size_t)(q0 + row) * HEAD_DIM + ch * 8;
        cp16(sb + FQ + so, Q + gq);
        size_t gk = hbase + (size_t)row * HEAD_DIM + ch * 8;
        cp16(sb + FK + so, K + gk);
        cp16(sb + FV + so, V + gk);
    }
    cp_commit();

    float o[16][4];
#pragma unroll
    for (int nb = 0; nb < 16; nb++)
#pragma unroll
        for (int r = 0; r < 4; r++) o[nb][r] = 0.f;
    float m0s = -1e30f, m1s = -1e30f, l0 = 0.f, l1 = 0.f;

    const float scale = 0.08838834764831845f;
    const int nt = q0 / 64 + 1;

    for (int kt = 0; kt < nt; kt++) {
        const int k0 = kt * 64;
        cp_wait_0();
        __syncthreads();

        float s[8][4];
#pragma unroll
        for (int ni = 0; ni < 8; ni++)
#pragma unroll
            for (int r = 0; r < 4; r++) s[ni][r] = 0.f;

#pragma unroll
        for (int kf = 0; kf < 8; kf++) {
            uint32_t aq[4];
            ldmatrix_x4(aq, sb + FQ + fsw(aRow, 2 * kf + aChS));
            uint32_t kb[8][2];
#pragma unroll
            for (int p = 0; p < 4; p++) {
                uint32_t t4[4];
                ldmatrix_x4(t4, sb + FK + fsw(p * 16 + bRowK, 2 * kf + bChK));
                kb[2*p][0] = t4[0]; kb[2*p][1] = t4[1];
                kb[2*p+1][0] = t4[2]; kb[2*p+1][1] = t4[3];
            }
#pragma unroll
            for (int ni = 0; ni < 8; ni++) mma_f16(s[ni], aq, kb[ni]);
        }

        const bool diag = (k0 == q0);
        const int row0 = q0 + w * 16 + gid;
        float mx0 = -1e30f, mx1 = -1e30f;
#pragma unroll
        for (int ni = 0; ni < 8; ni++) {
#pragma unroll
            for (int r = 0; r < 4; r++) {
                float v = s[ni][r] * scale;
                if (diag) {
                    int col = k0 + ni * 8 + tig * 2 + (r & 1);
                    int row = row0 + ((r >> 1) << 3);
                    if (col > row) v = -1e30f;
                }
                s[ni][r] = v;
                if (r < 2) mx0 = fmaxf(mx0, v); else mx1 = fmaxf(mx1, v);
            }
        }
        mx0 = fmaxf(mx0, __shfl_xor_sync(0xffffffffu, mx0, 1));
        mx0 = fmaxf(mx0, __shfl_xor_sync(0xffffffffu, mx0, 2));
        mx1 = fmaxf(mx1, __shfl_xor_sync(0xffffffffu, mx1, 1));
        mx1 = fmaxf(mx1, __shfl_xor_sync(0xffffffffu, mx1, 2));

        float mn0 = fmaxf(m0s, mx0), mn1 = fmaxf(m1s, mx1);
        float a0 = __expf(m0s - mn0), a1 = __expf(m1s - mn1);
        float ls0 = 0.f, ls1 = 0.f;
#pragma unroll
        for (int ni = 0; ni < 8; ni++) {
            s[ni][0] = __expf(s[ni][0] - mn0); ls0 += s[ni][0];
            s[ni][1] = __expf(s[ni][1] - mn0); ls0 += s[ni][1];
            s[ni][2] = __expf(s[ni][2] - mn1); ls1 += s[ni][2];
            s[ni][3] = __expf(s[ni][3] - mn1); ls1 += s[ni][3];
        }
        ls0 += __shfl_xor_sync(0xffffffffu, ls0, 1);
        ls0 += __shfl_xor_sync(0xffffffffu, ls0, 2);
        ls1 += __shfl_xor_sync(0xffffffffu, ls1, 1);
        ls1 += __shfl_xor_sync(0xffffffffu, ls1, 2);
        l0 = l0 * a0 + ls0; l1 = l1 * a1 + ls1;
        m0s = mn0; m1s = mn1;
#pragma unroll
        for (int nb = 0; nb < 16; nb++) {
            o[nb][0] *= a0; o[nb][1] *= a0; o[nb][2] *= a1; o[nb][3] *= a1;
        }

        uint32_t P[4][4];
#pragma unroll
        for (int j = 0; j < 4; j++) {
            P[j][0] = pack_h2(s[2*j][0],   s[2*j][1]);
            P[j][1] = pack_h2(s[2*j][2],   s[2*j][3]);
            P[j][2] = pack_h2(s[2*j+1][0], s[2*j+1][1]);
            P[j][3] = pack_h2(s[2*j+1][2], s[2*j+1][3]);
        }

#pragma unroll
        for (int j = 0; j < 4; j++) {
#pragma unroll
            for (int p = 0; p < 8; p++) {
                uint32_t t4[4];
                ldmatrix_x4_t(t4, sb + FV + fsw(j * 16 + vRowS, 2 * p + vChS));
                uint32_t b0[2] = {t4[0], t4[1]}, b1[2] = {t4[2], t4[3]};
                mma_f16(o[2*p],   P[j], b0);
                mma_f16(o[2*p+1], P[j], b1);
            }
        }

        if (kt + 1 < nt) {
            __syncthreads();
            const int nk0 = (kt + 1) * 64;
#pragma unroll
            for (int j = 0; j < 8; j++) {
                int idx = tid + 128 * j; int row = idx >> 4; int ch = idx & 15;
                uint32_t so = fsw(row, ch);
                size_t gk = hbase + (size_t)(nk0 + row) * HEAD_DIM + ch * 8;
                cp16(sb + FK + so, K + gk);
                cp16(sb + FV + so, V + gk);
            }
            cp_commit();
        }
    }

    float i0 = 1.0f / l0, i1 = 1.0f / l1;
    const int b = bh >> 4, h = bh & 15;
    size_t t0 = (size_t)(b * SEQ + q0 + w * 16 + gid) * D_MODEL + h * HEAD_DIM;
    size_t t1 = t0 + (size_t)8 * D_MODEL;
#pragma unroll
    for (int nb = 0; nb < 16; nb++) {
        int col = nb * 8 + tig * 2;
        *(__half2*)(Ctx + t0 + col) = __floats2half2_rn(o[nb][0] * i0, o[nb][1] * i0);
        *(__half2*)(Ctx + t1 + col) = __floats2half2_rn(o[nb][2] * i1, o[nb][3] * i1);
    }
}

// ============================================================================
// launch
// ============================================================================
extern "C" void kernel_launch(void* const* d_in, const int* in_sizes, int n_in,
                              void* d_out, int out_size)
{
    const float* x   = (const float*)d_in[0];
    const int*   pos = (const int*)  d_in[1];
    const float* Wq  = (const float*)d_in[2];
    const float* Wk  = (const float*)d_in[3];
    const float* Wv  = (const float*)d_in[4];
    const float* Wo  = (const float*)d_in[5];
    float* out = (float*)d_out;

    __half *xf, *cf, *Wqkvf, *Wof, *fQ, *fK, *fV;
    float2* tab;
    cudaGetSymbolAddress((void**)&xf, g_xf);
    cudaGetSymbolAddress((void**)&cf, g_cf);
    cudaGetSymbolAddress((void**)&Wqkvf, g_Wqkvf);
    cudaGetSymbolAddress((void**)&Wof, g_Wof);
    cudaGetSymbolAddress((void**)&fQ, g_fQ);
    cudaGetSymbolAddress((void**)&fK, g_fK);
    cudaGetSymbolAddress((void**)&fV, g_fV);
    cudaGetSymbolAddress((void**)&tab, g_tab);

    cudaFuncSetAttribute(mma_gemmQKV_kernel,
                         cudaFuncAttributeMaxDynamicSharedMemorySize, SMEM_G64);
    cudaFuncSetAttribute(mma_gemm1_kernel,
                         cudaFuncAttributeMaxDynamicSharedMemorySize, SMEM_G64);
    cudaFuncSetAttribute(flash2_kernel,
                         cudaFuncAttributeMaxDynamicSharedMemorySize, SMEM_FLASH);

    const int x_n4 = (M_TOT * D_MODEL) / 4;
    const int w_n4 = (D_MODEL * D_MODEL) / 4;

    // conversions + rope table
    cvt_h_kernel<<<(x_n4 + 255) / 256, 256>>>(x, xf, x_n4);
    dim3 wGrid((w_n4 + 255) / 256, 4);
    cvt_w4_kernel<<<wGrid, 256>>>(Wq, Wk, Wv, Wo, Wqkvf, Wof, w_n4);
    rope_tab_kernel<<<(M_TOT * 64 + 255) / 256, 256>>>(pos, tab);

    // fused QKV projection (fp16, CTA 128x256) + RoPE epilogue -> fp16 head-major
    dim3 qkvGrid(N_QKV / 256, M_TOT / 128);     // (24, 32)
    mma_gemmQKV_kernel<<<qkvGrid, 256, SMEM_G64>>>(xf, Wqkvf, tab, fQ, fK, fV);

    // all-fp16 tensor-core flash attention -> fp16 ctx (token-major)
    dim3 fGrid(SEQ / 64, N_BH);                 // (32, 32)
    flash2_kernel<<<fGrid, 128, SMEM_FLASH>>>(fQ, fK, fV, cf);

    // output projection (fp16) -> fp32 out
    dim3 oGrid(D_MODEL / 256, M_TOT / 128);     // (8, 32)
    mma_gemm1_kernel<<<oGrid, 256, SMEM_G64>>>(cf, Wof, out, D_MODEL);
}